// round 6
// baseline (speedup 1.0000x reference)
#include <cuda_runtime.h>

#define HID   100
#define G4    400
#define SEQ   8192
#define NCLS  20
#define TB    16
#define NTL   512      // 5 slices x 100 + 12 inert lanes; 16 warps -> 128-reg cap
#define KS    20       // floats per K-slice
#define PADH  128      // padded h (inert lanes read junk harmlessly)

// scratch for x_proj, stored TRANSPOSED: xp4[t*100 + j] = (i,f,g,o) of unit j
__device__ float4 g_xp4[SEQ * HID];

__device__ __forceinline__ unsigned long long ffma2(unsigned long long a,
                                                    unsigned long long b,
                                                    unsigned long long c) {
    unsigned long long d;
    asm("fma.rn.f32x2 %0, %1, %2, %3;" : "=l"(d) : "l"(a), "l"(b), "l"(c));
    return d;
}
__device__ __forceinline__ unsigned long long addf2(unsigned long long a,
                                                    unsigned long long b) {
    unsigned long long d;
    asm("add.rn.f32x2 %0, %1, %2;" : "=l"(d) : "l"(a), "l"(b));
    return d;
}
__device__ __forceinline__ void unpack2(unsigned long long v, float& lo, float& hi) {
    asm("mov.b64 {%0, %1}, %2;" : "=f"(lo), "=f"(hi) : "l"(v));
}
__device__ __forceinline__ unsigned long long pack2(float lo, float hi) {
    unsigned long long v;
    asm("mov.b64 %0, {%1, %2};" : "=l"(v) : "f"(lo), "f"(hi));
    return v;
}
__device__ __forceinline__ float sig_f(float x) {
    float e = exp2f(x * -1.442695041f);
    return __fdividef(1.f, 1.f + e);
}
__device__ __forceinline__ float tanh_f(float x) {
    float e = exp2f(x * -2.885390082f);
    return __fdividef(2.f, 1.f + e) - 1.f;
}

// ---------------------------------------------------------------------------
// Kernel 1: embedding gather + x_proj GEMM, TRANSPOSED output (i,f,g,o)/unit
// ---------------------------------------------------------------------------
__global__ void __launch_bounds__(G4, 1)
proj_kernel(const int* __restrict__ seq, const float* __restrict__ emb,
            const float* __restrict__ W_ih, const float* __restrict__ b_ih,
            const float* __restrict__ b_hh) {
    __shared__ float es[TB * HID];
    __shared__ int   sid[TB];
    const int tid = threadIdx.x;          // gate row r = g*100 + j
    const int t0  = blockIdx.x * TB;
    const int g   = tid / HID;
    const int j   = tid - g * HID;

    if (tid < TB) sid[tid] = seq[t0 + tid];
    __syncthreads();
    for (int n = tid; n < TB * HID; n += G4) {
        int tt = n / HID, k = n % HID;
        es[n] = emb[(long long)sid[tt] * HID + k];
    }
    __syncthreads();

    float acc[TB];
#pragma unroll
    for (int tt = 0; tt < TB; tt++) acc[tt] = 0.f;

    const float4* wr4 = (const float4*)(W_ih + tid * HID);
#pragma unroll 5
    for (int m = 0; m < 25; m++) {
        float4 wv = __ldg(&wr4[m]);
#pragma unroll
        for (int tt = 0; tt < TB; tt++) {
            const float* e = es + tt * HID + 4 * m;
            acc[tt] += wv.x * e[0] + wv.y * e[1] + wv.z * e[2] + wv.w * e[3];
        }
    }
    float b = b_ih[tid] + b_hh[tid];
    float* xp = (float*)g_xp4;
#pragma unroll
    for (int tt = 0; tt < TB; tt++)
        xp[(t0 + tt) * G4 + j * 4 + g] = acc[tt] + b;   // transposed
}

// ---------------------------------------------------------------------------
// Kernel 2: LSTM recurrence — 512 threads (500 active), slice-major.
// tid = s*100 + j. Thread owns all 4 gate rows of unit j over K-slice
// [20s, 20s+20): 40 f32x2 weight regs. Owners (tid<100, warps 0-3) reduce
// partials with packed f32x2 adds, activate exactly, update c and h.
// Sync: workers bar.arrive(1) (non-blocking) -> owners bar.sync(1) wake
// alone; one full __syncthreads gates the h handoff.
// ---------------------------------------------------------------------------
__global__ void __launch_bounds__(NTL, 1)
lstm_kernel(const float* __restrict__ W_hh,
            const float* __restrict__ fc_w, const float* __restrict__ fc_b,
            float* __restrict__ out) {
    __shared__ __align__(16) float h_sh[PADH];
    __shared__ __align__(16) float4 part4[NTL];
    const int tid = threadIdx.x;
    const int s   = tid / HID;            // K-slice 0..4 (5 for inert lanes)
    const int j   = tid - s * HID;
    const bool owner     = (tid < HID);
    const bool syncgroup = (tid < 128);   // warps 0-3: uniform bar.sync

    // preload weights: 4 gate rows x 5 float4 chunks of this slice
    // (inert lanes s=5 read in-bounds junk, results never consumed)
    unsigned long long w2[40];
#pragma unroll
    for (int g = 0; g < 4; g++) {
        const float* wrow = W_hh + (g * HID + j) * HID + KS * s;
#pragma unroll
        for (int m = 0; m < 5; m++) {
            float4 v = *(const float4*)(wrow + 4 * m);
            w2[g * 10 + 2 * m]     = pack2(v.x, v.y);
            w2[g * 10 + 2 * m + 1] = pack2(v.z, v.w);
        }
    }

    for (int n = tid; n < PADH; n += NTL) h_sh[n] = 0.f;
    float c = 0.f;
    __syncthreads();

    ulonglong2 xq;
    if (owner) xq = *(const ulonglong2*)&g_xp4[j];   // t = 0 (L2-hot)

    for (int t = 0; t < SEQ; t++) {
        ulonglong2 xq_n;
        if (owner)
            xq_n = *(const ulonglong2*)&g_xp4[((t + 1) & (SEQ - 1)) * HID + j];

        // matvec slice: 5 broadcast LDS.128 + 40 FFMA2, one acc per gate
        unsigned long long a0 = 0ull, a1 = 0ull, a2 = 0ull, a3 = 0ull;
        const ulonglong2* h2 = (const ulonglong2*)h_sh;
#pragma unroll
        for (int m = 0; m < 5; m++) {
            ulonglong2 hv = h2[5 * s + m];     // all 32 lanes same addr
            a0 = ffma2(w2[2 * m],      hv.x, a0);
            a0 = ffma2(w2[2 * m + 1],  hv.y, a0);
            a1 = ffma2(w2[10 + 2 * m], hv.x, a1);
            a1 = ffma2(w2[11 + 2 * m], hv.y, a1);
            a2 = ffma2(w2[20 + 2 * m], hv.x, a2);
            a2 = ffma2(w2[21 + 2 * m], hv.y, a2);
            a3 = ffma2(w2[30 + 2 * m], hv.x, a3);
            a3 = ffma2(w2[31 + 2 * m], hv.y, a3);
        }
        float l0, h0, l1, h1, l2, h2v, l3, h3;
        unpack2(a0, l0, h0);
        unpack2(a1, l1, h1);
        unpack2(a2, l2, h2v);
        unpack2(a3, l3, h3);

        if (!owner)   // workers (incl. inert) publish packed partials
            part4[tid] = make_float4(l0 + h0, l1 + h1, l2 + h2v, l3 + h3);

        if (syncgroup) {
            asm volatile("bar.sync 1, %0;" :: "n"(NTL) : "memory");
            if (owner) {
                // packed reduction: (i,f) and (g,o) pairs
                unsigned long long pif = pack2(l0 + h0, l1 + h1);
                unsigned long long pgo = pack2(l2 + h2v, l3 + h3);
#pragma unroll
                for (int sp = 1; sp < 5; sp++) {
                    ulonglong2 v = *(const ulonglong2*)&part4[sp * HID + j];
                    pif = addf2(pif, v.x);
                    pgo = addf2(pgo, v.y);
                }
                pif = addf2(pif, xq.x);
                pgo = addf2(pgo, xq.y);
                float pi, pf, pg, po;
                unpack2(pif, pi, pf);
                unpack2(pgo, pg, po);

                float ig = sig_f(pi);
                float fg = sig_f(pf);
                float gg = tanh_f(pg);
                float og = sig_f(po);
                c = fg * c + ig * gg;
                h_sh[j] = og * tanh_f(c);
                xq = xq_n;
            }
        } else {
            asm volatile("bar.arrive 1, %0;" :: "n"(NTL) : "memory");
        }
        __syncthreads();   // h handoff
    }

    // final FC
    if (tid < NCLS) {
        float sfc = fc_b[tid];
        const float* fw = fc_w + tid * HID;
#pragma unroll 4
        for (int k = 0; k < HID; k++) sfc += fw[k] * h_sh[k];
        out[tid] = sfc;
    }
}

// ---------------------------------------------------------------------------
extern "C" void kernel_launch(void* const* d_in, const int* in_sizes, int n_in,
                              void* d_out, int out_size) {
    const int*   seq  = (const int*)d_in[0];
    const float* emb  = (const float*)d_in[1];
    const float* W_ih = (const float*)d_in[2];
    const float* W_hh = (const float*)d_in[3];
    const float* b_ih = (const float*)d_in[4];
    const float* b_hh = (const float*)d_in[5];
    const float* fc_w = (const float*)d_in[6];
    const float* fc_b = (const float*)d_in[7];
    float* out = (float*)d_out;

    proj_kernel<<<SEQ / TB, G4>>>(seq, emb, W_ih, b_ih, b_hh);
    lstm_kernel<<<1, NTL>>>(W_hh, fc_w, fc_b, out);
}

// round 7
// speedup vs baseline: 1.0749x; 1.0749x over previous
#include <cuda_runtime.h>

#define HID   100
#define G4    400
#define SEQ   8192
#define NCLS  20
#define TB    16
#define NTL   500      // 5 K-slices x 100 units; 16-warp alloc -> 128-reg cap
#define KS    20       // floats per K-slice (5*20 = 100, exact)

// scratch for x_proj, stored TRANSPOSED: xp4[t*100 + j] = (i,f,g,o) of unit j
__device__ float4 g_xp4[SEQ * HID];

__device__ __forceinline__ unsigned long long ffma2(unsigned long long a,
                                                    unsigned long long b,
                                                    unsigned long long c) {
    unsigned long long d;
    asm("fma.rn.f32x2 %0, %1, %2, %3;" : "=l"(d) : "l"(a), "l"(b), "l"(c));
    return d;
}
__device__ __forceinline__ unsigned long long addf2(unsigned long long a,
                                                    unsigned long long b) {
    unsigned long long d;
    asm("add.rn.f32x2 %0, %1, %2;" : "=l"(d) : "l"(a), "l"(b));
    return d;
}
__device__ __forceinline__ void unpack2(unsigned long long v, float& lo, float& hi) {
    asm("mov.b64 {%0, %1}, %2;" : "=f"(lo), "=f"(hi) : "l"(v));
}
__device__ __forceinline__ unsigned long long pack2(float lo, float hi) {
    unsigned long long v;
    asm("mov.b64 %0, {%1, %2};" : "=l"(v) : "f"(lo), "f"(hi));
    return v;
}
__device__ __forceinline__ float sig_f(float x) {
    float e = exp2f(x * -1.442695041f);
    return __fdividef(1.f, 1.f + e);
}
__device__ __forceinline__ float tanh_f(float x) {
    float e = exp2f(x * -2.885390082f);
    return __fdividef(2.f, 1.f + e) - 1.f;
}

// ---------------------------------------------------------------------------
// Kernel 1: embedding gather + x_proj GEMM, TRANSPOSED output (i,f,g,o)/unit
// ---------------------------------------------------------------------------
__global__ void __launch_bounds__(G4, 1)
proj_kernel(const int* __restrict__ seq, const float* __restrict__ emb,
            const float* __restrict__ W_ih, const float* __restrict__ b_ih,
            const float* __restrict__ b_hh) {
    __shared__ float es[TB * HID];
    __shared__ int   sid[TB];
    const int tid = threadIdx.x;          // gate row r = g*100 + j
    const int t0  = blockIdx.x * TB;
    const int g   = tid / HID;
    const int j   = tid - g * HID;

    if (tid < TB) sid[tid] = seq[t0 + tid];
    __syncthreads();
    for (int n = tid; n < TB * HID; n += G4) {
        int tt = n / HID, k = n % HID;
        es[n] = emb[(long long)sid[tt] * HID + k];
    }
    __syncthreads();

    float acc[TB];
#pragma unroll
    for (int tt = 0; tt < TB; tt++) acc[tt] = 0.f;

    const float4* wr4 = (const float4*)(W_ih + tid * HID);
#pragma unroll 5
    for (int m = 0; m < 25; m++) {
        float4 wv = __ldg(&wr4[m]);
#pragma unroll
        for (int tt = 0; tt < TB; tt++) {
            const float* e = es + tt * HID + 4 * m;
            acc[tt] += wv.x * e[0] + wv.y * e[1] + wv.z * e[2] + wv.w * e[3];
        }
    }
    float b = b_ih[tid] + b_hh[tid];
    float* xp = (float*)g_xp4;
#pragma unroll
    for (int tt = 0; tt < TB; tt++)
        xp[(t0 + tt) * G4 + j * 4 + g] = acc[tt] + b;   // transposed
}

// ---------------------------------------------------------------------------
// Kernel 2: LSTM recurrence — 500 threads, slice-major (R5 skeleton).
// tid = s*100 + j. Thread owns all 4 gate rows of unit j over K-slice
// [20s, 20s+20): 40 f32x2 weight regs, spill-free. Owners (tid<100)
// reduce partials with packed f32x2 adds, activate exactly (EX2/RCP),
// update c and h. Two full __syncthreads per step (proven fastest sync).
// ---------------------------------------------------------------------------
__global__ void __launch_bounds__(NTL, 1)
lstm_kernel(const float* __restrict__ W_hh,
            const float* __restrict__ fc_w, const float* __restrict__ fc_b,
            float* __restrict__ out) {
    __shared__ __align__(16) float h_sh[HID + 4];
    __shared__ __align__(16) float4 part4[NTL];
    const int tid = threadIdx.x;
    const int s   = tid / HID;            // K-slice 0..4
    const int j   = tid - s * HID;        // unit 0..99
    const bool owner = (tid < HID);

    // preload weights: 4 gate rows x 5 float4 chunks of this slice
    unsigned long long w2[40];
#pragma unroll
    for (int g = 0; g < 4; g++) {
        const float* wrow = W_hh + (g * HID + j) * HID + KS * s;
#pragma unroll
        for (int m = 0; m < 5; m++) {
            float4 v = *(const float4*)(wrow + 4 * m);
            w2[g * 10 + 2 * m]     = pack2(v.x, v.y);
            w2[g * 10 + 2 * m + 1] = pack2(v.z, v.w);
        }
    }

    for (int n = tid; n < HID + 4; n += NTL) h_sh[n] = 0.f;
    float c = 0.f;
    __syncthreads();

    // strength-reduced x_proj pointer (owner only), prefetched a step ahead
    const ulonglong2* xp = (const ulonglong2*)&g_xp4[j];
    ulonglong2 xq;
    if (owner) xq = *xp;
    xp += HID;

    const ulonglong2* h2 = (const ulonglong2*)h_sh + 5 * s;

    for (int t = 0; t < SEQ; t++) {
        ulonglong2 xq_n;
        if (owner && t + 1 < SEQ) xq_n = xp[0];

        // matvec slice: 5 broadcast LDS.128 + 40 FFMA2, one acc per gate
        unsigned long long a0 = 0ull, a1 = 0ull, a2 = 0ull, a3 = 0ull;
#pragma unroll
        for (int m = 0; m < 5; m++) {
            ulonglong2 hv = h2[m];             // all 32 lanes same addr
            a0 = ffma2(w2[2 * m],      hv.x, a0);
            a0 = ffma2(w2[2 * m + 1],  hv.y, a0);
            a1 = ffma2(w2[10 + 2 * m], hv.x, a1);
            a1 = ffma2(w2[11 + 2 * m], hv.y, a1);
            a2 = ffma2(w2[20 + 2 * m], hv.x, a2);
            a2 = ffma2(w2[21 + 2 * m], hv.y, a2);
            a3 = ffma2(w2[30 + 2 * m], hv.x, a3);
            a3 = ffma2(w2[31 + 2 * m], hv.y, a3);
        }
        float l0, h0, l1, h1, l2, h2v, l3, h3;
        unpack2(a0, l0, h0);
        unpack2(a1, l1, h1);
        unpack2(a2, l2, h2v);
        unpack2(a3, l3, h3);

        if (!owner)
            part4[tid] = make_float4(l0 + h0, l1 + h1, l2 + h2v, l3 + h3);
        __syncthreads();

        if (owner) {
            // packed reduction over 4 worker slices + x_proj
            unsigned long long pif = pack2(l0 + h0, l1 + h1);
            unsigned long long pgo = pack2(l2 + h2v, l3 + h3);
#pragma unroll
            for (int sp = 1; sp < 5; sp++) {
                ulonglong2 v = *(const ulonglong2*)&part4[sp * HID + j];
                pif = addf2(pif, v.x);
                pgo = addf2(pgo, v.y);
            }
            pif = addf2(pif, xq.x);
            pgo = addf2(pgo, xq.y);
            float pi, pf, pg, po;
            unpack2(pif, pi, pf);
            unpack2(pgo, pg, po);

            float ig = sig_f(pi);
            float fg = sig_f(pf);
            float gg = tanh_f(pg);
            float og = sig_f(po);
            c = fg * c + ig * gg;
            h_sh[j] = og * tanh_f(c);
            xq = xq_n;
        }
        __syncthreads();
        xp += HID;
    }

    // final FC
    if (tid < NCLS) {
        float sfc = fc_b[tid];
        const float* fw = fc_w + tid * HID;
#pragma unroll 4
        for (int k = 0; k < HID; k++) sfc += fw[k] * h_sh[k];
        out[tid] = sfc;
    }
}

// ---------------------------------------------------------------------------
extern "C" void kernel_launch(void* const* d_in, const int* in_sizes, int n_in,
                              void* d_out, int out_size) {
    const int*   seq  = (const int*)d_in[0];
    const float* emb  = (const float*)d_in[1];
    const float* W_ih = (const float*)d_in[2];
    const float* W_hh = (const float*)d_in[3];
    const float* b_ih = (const float*)d_in[4];
    const float* b_hh = (const float*)d_in[5];
    const float* fc_w = (const float*)d_in[6];
    const float* fc_b = (const float*)d_in[7];
    float* out = (float*)d_out;

    proj_kernel<<<SEQ / TB, G4>>>(seq, emb, W_ih, b_ih, b_hh);
    lstm_kernel<<<1, NTL>>>(W_hh, fc_w, fc_b, out);
}